// round 12
// baseline (speedup 1.0000x reference)
#include <cuda_runtime.h>
#include <cuda_fp16.h>
#include <math.h>

#define NN      4096
#define IN_DIM  128
#define HEADS   4
#define OUT_DIM 64
#define HD      256   // HEADS*OUT_DIM
#define NB      512   // gather chunk size
#define NBP     (NB + 8)
#define SEG     1024  // csr segment length (ints)

// persistent scratch (allocation-free rule: __device__ globals)
__device__ uint4          g_hb[NN * 32];           // h in fp16: 4096 x 256 x 2B = 2 MB
__device__ float          g_si[NN * HEADS];
__device__ float          g_sj[NN * HEADS];
__device__ float          g_mx[HEADS];
__device__ unsigned short g_nbr[(size_t)NN * NN];  // 4 segments of 1024 per row
__device__ int            g_cnt4[NN * 4];

// ---- packed f32x2 helpers (documented sm_103a PTX: fma.rn.f32x2) ----
__device__ __forceinline__ unsigned long long pack_f32x2(float lo, float hi) {
    unsigned long long r;
    asm("mov.b64 %0, {%1, %2};" : "=l"(r) : "f"(lo), "f"(hi));
    return r;
}
__device__ __forceinline__ void unpack_f32x2(float& lo, float& hi, unsigned long long v) {
    asm("mov.b64 {%0, %1}, %2;" : "=f"(lo), "=f"(hi) : "l"(v));
}
// acc(f32x2) += f32x2(h2) * p2
__device__ __forceinline__ void ffma2_h(unsigned long long& acc,
                                        unsigned int h2, unsigned long long p2) {
    __half2 hh = *reinterpret_cast<__half2*>(&h2);
    float2 f = __half22float2(hh);
    unsigned long long hf = pack_f32x2(f.x, f.y);
    asm("fma.rn.f32x2 %0, %1, %2, %0;" : "+l"(acc) : "l"(hf), "l"(p2));
}

// --------------------------------------------------------------------------
// Kernel 1: h = x @ W (fp16 out) + fused scores. 16 rows/blk, manual MLP=8.
// --------------------------------------------------------------------------
__global__ __launch_bounds__(256) void gemm_h_kernel(const float* __restrict__ x,
                                                     const float* __restrict__ W,
                                                     const float* __restrict__ a_src,
                                                     const float* __restrict__ a_dst) {
    __shared__ float xs[16][IN_DIM];
    __shared__ float s_si[16][HEADS];
    __shared__ float s_sj[16][HEADS];
    const int t = threadIdx.x;
    const int row0 = blockIdx.x * 16;

    for (int idx = t; idx < 16 * IN_DIM; idx += 256)
        xs[idx >> 7][idx & 127] = x[row0 * IN_DIM + idx];
    if (t < 64) { s_si[t >> 2][t & 3] = 0.f; s_sj[t >> 2][t & 3] = 0.f; }
    __syncthreads();

    const int slot = t & 63;
    const int grp  = t >> 6;
    float4 acc[4];
#pragma unroll
    for (int r = 0; r < 4; r++) acc[r] = make_float4(0.f, 0.f, 0.f, 0.f);

    const float4* W4 = (const float4*)W;
#pragma unroll
    for (int kc = 0; kc < IN_DIM; kc += 8) {
        float4 wv[8];
#pragma unroll
        for (int u = 0; u < 8; u++) wv[u] = W4[(kc + u) * 64 + slot];   // MLP=8
#pragma unroll
        for (int u = 0; u < 8; u++) {
#pragma unroll
            for (int r = 0; r < 4; r++) {
                float xv = xs[grp * 4 + r][kc + u];
                acc[r].x = fmaf(xv, wv[u].x, acc[r].x);
                acc[r].y = fmaf(xv, wv[u].y, acc[r].y);
                acc[r].z = fmaf(xv, wv[u].z, acc[r].z);
                acc[r].w = fmaf(xv, wv[u].w, acc[r].w);
            }
        }
    }
    __half2* HB = (__half2*)g_hb;
#pragma unroll
    for (int r = 0; r < 4; r++) {
        int row = row0 + grp * 4 + r;
        HB[(size_t)row * 128 + slot * 2]     = __floats2half2_rn(acc[r].x, acc[r].y);
        HB[(size_t)row * 128 + slot * 2 + 1] = __floats2half2_rn(acc[r].z, acc[r].w);
    }
    const int d0 = (slot * 4) & 63;
    const int hh = slot >> 4;
    float as0 = a_src[d0], as1 = a_src[d0 + 1], as2 = a_src[d0 + 2], as3 = a_src[d0 + 3];
    float ad0 = a_dst[d0], ad1 = a_dst[d0 + 1], ad2 = a_dst[d0 + 2], ad3 = a_dst[d0 + 3];
#pragma unroll
    for (int r = 0; r < 4; r++) {
        float psi = acc[r].x * as0 + acc[r].y * as1 + acc[r].z * as2 + acc[r].w * as3;
        float psj = acc[r].x * ad0 + acc[r].y * ad1 + acc[r].z * ad2 + acc[r].w * ad3;
        atomicAdd(&s_si[grp * 4 + r][hh], psi);
        atomicAdd(&s_sj[grp * 4 + r][hh], psj);
    }
    __syncthreads();
    if (t < 64) {
        g_si[(row0 + (t >> 2)) * HEADS + (t & 3)] = s_si[t >> 2][t & 3];
        g_sj[(row0 + (t >> 2)) * HEADS + (t & 3)] = s_sj[t >> 2][t & 3];
    }
}

// --------------------------------------------------------------------------
// Kernel 2: standalone CSR build, MLP=8. 1 warp = 1 segment of 1024 ints.
// --------------------------------------------------------------------------
__global__ __launch_bounds__(256) void csr_kernel(const int* __restrict__ mask) {
    const int warp = threadIdx.x >> 5, lane = threadIdx.x & 31;
    const int segIdx = blockIdx.x * 8 + warp;
    const int row = segIdx >> 2, seg = segIdx & 3;

    const int4* m4 = (const int4*)mask + (size_t)row * (NN / 4) + seg * 256;
    unsigned short* dst = g_nbr + (size_t)row * NN + seg * SEG;

    int4 v[8];
#pragma unroll
    for (int it = 0; it < 8; it++) v[it] = m4[it * 32 + lane];   // MLP=8

    int base = 0;
    const int jb0 = seg * SEG;
#pragma unroll
    for (int it = 0; it < 8; it++) {
        int b0 = (v[it].x != 0), b1 = (v[it].y != 0);
        int b2 = (v[it].z != 0), b3 = (v[it].w != 0);
        int mycnt = b0 + b1 + b2 + b3;
        int incl = mycnt;
#pragma unroll
        for (int d = 1; d < 32; d <<= 1) {
            int nn = __shfl_up_sync(0xffffffffu, incl, d);
            if (lane >= d) incl += nn;
        }
        int total = __shfl_sync(0xffffffffu, incl, 31);
        int off = incl - mycnt;
        int jb  = jb0 + (it * 32 + lane) * 4;
        int pos = base + off;
        if (b0) dst[pos++] = (unsigned short)(jb);
        if (b1) dst[pos++] = (unsigned short)(jb + 1);
        if (b2) dst[pos++] = (unsigned short)(jb + 2);
        if (b3) dst[pos++] = (unsigned short)(jb + 3);
        base += total;
    }
    if (lane == 0) g_cnt4[segIdx] = base;
}

// --------------------------------------------------------------------------
// Kernel 3: g_mx[h] = max_n g_sj[n][h]. One block.
// --------------------------------------------------------------------------
__global__ __launch_bounds__(256) void max_sj_kernel() {
    __shared__ float red[HEADS][8];
    const int t = threadIdx.x, lane = t & 31, wid = t >> 5;
    float mx[HEADS];
#pragma unroll
    for (int h = 0; h < HEADS; h++) mx[h] = -INFINITY;
    const float4* s4 = (const float4*)g_sj;
    for (int i = t; i < NN; i += 256) {
        float4 v = s4[i];
        mx[0] = fmaxf(mx[0], v.x); mx[1] = fmaxf(mx[1], v.y);
        mx[2] = fmaxf(mx[2], v.z); mx[3] = fmaxf(mx[3], v.w);
    }
#pragma unroll
    for (int h = 0; h < HEADS; h++)
#pragma unroll
        for (int d = 16; d; d >>= 1)
            mx[h] = fmaxf(mx[h], __shfl_xor_sync(0xffffffffu, mx[h], d));
    if (lane == 0)
#pragma unroll
        for (int h = 0; h < HEADS; h++) red[h][wid] = mx[h];
    __syncthreads();
    if (t < HEADS) {
        float m = red[t][0];
#pragma unroll
        for (int w = 1; w < 8; w++) m = fmaxf(m, red[t][w]);
        g_mx[t] = m;
    }
}

// --------------------------------------------------------------------------
// Kernel 4: sparse gather attention. Acc-pass: warp-contiguous spans,
// batched idx/p loads, F2F + packed fma.rn.f32x2 (fp32 accumulation).
// --------------------------------------------------------------------------
__global__ __launch_bounds__(256) void gather_kernel(float* __restrict__ out) {
    __shared__ __align__(16) unsigned short nbr[NN];
    __shared__ __align__(16) float p_sh[HEADS][NBP];
    __shared__ float acc_sh[8][32][8];
    __shared__ float red_sh[HEADS][8];
    __shared__ float tot_sh[HEADS];

    const int t    = threadIdx.x;
    const int lane = t & 31;
    const int wid  = t >> 5;
    const int row  = blockIdx.x;
    const int c    = t & 31;      // 16B chunk of the 512B fp16 row
    const int q    = t >> 5;      // warp id = j-span owner
    const int hc   = c >> 3;      // head owned in acc pass

    // ---- stage + compact 4 segments ----
    int c4[4];
#pragma unroll
    for (int s = 0; s < 4; s++) c4[s] = g_cnt4[row * 4 + s];
    int o1 = c4[0], o2 = o1 + c4[1], o3 = o2 + c4[2];
    int cnt = o3 + c4[3];
    const unsigned short* nrow = g_nbr + (size_t)row * NN;
    const bool uniform = (cnt == 0);
    if (uniform) {
        for (int jj = t; jj < NN; jj += 256) nbr[jj] = (unsigned short)jj;
        cnt = NN;
    } else {
        for (int jj = t; jj < c4[0]; jj += 256) nbr[jj]      = nrow[jj];
        for (int jj = t; jj < c4[1]; jj += 256) nbr[o1 + jj] = nrow[SEG + jj];
        for (int jj = t; jj < c4[2]; jj += 256) nbr[o2 + jj] = nrow[2 * SEG + jj];
        for (int jj = t; jj < c4[3]; jj += 256) nbr[o3 + jj] = nrow[3 * SEG + jj];
    }

    // ---- per-row factors ----
    float si[HEADS], m[HEADS];
#pragma unroll
    for (int h = 0; h < HEADS; h++) {
        si[h] = g_si[row * HEADS + h];
        float v = si[h] + g_mx[h];
        m[h] = fmaxf(v, 0.2f * v);        // lrelu, >= all row scores
    }
    float sum[HEADS] = {0.f, 0.f, 0.f, 0.f};
    unsigned long long acc01 = 0ull, acc23 = 0ull, acc45 = 0ull, acc67 = 0ull;

    const float4* gsj4 = (const float4*)g_sj;
    const uint4*  hb_c = g_hb + c;
    __syncthreads();

    for (int base = 0; base < cnt; base += NB) {
        const int cn = min(NB, cnt - base);

        // ---- p-pass ----
        for (int jj = t; jj < cn; jj += 256) {
            float4 sj = gsj4[nbr[base + jj]];
            float e0 = si[0] + sj.x; e0 = fmaxf(e0, 0.2f * e0);
            float e1 = si[1] + sj.y; e1 = fmaxf(e1, 0.2f * e1);
            float e2 = si[2] + sj.z; e2 = fmaxf(e2, 0.2f * e2);
            float e3 = si[3] + sj.w; e3 = fmaxf(e3, 0.2f * e3);
            float p0 = uniform ? 1.f : __expf(e0 - m[0]);
            float p1 = uniform ? 1.f : __expf(e1 - m[1]);
            float p2 = uniform ? 1.f : __expf(e2 - m[2]);
            float p3 = uniform ? 1.f : __expf(e3 - m[3]);
            p_sh[0][jj] = p0; p_sh[1][jj] = p1;
            p_sh[2][jj] = p2; p_sh[3][jj] = p3;
            sum[0] += p0; sum[1] += p1; sum[2] += p2; sum[3] += p3;
        }
        __syncthreads();

        // ---- acc-pass: warp-contiguous span, 4-edge batches ----
        const int sp = (((cn + 7) >> 3) + 3) & ~3;   // span per warp, mult of 4
        const int lo = q * sp;
        const int hi = min(lo + sp, cn);
        int jj = lo;
#pragma unroll 2
        for (; jj + 4 <= hi; jj += 4) {
            uint2  i4 = *(const uint2*)(nbr + base + jj);
            float4 pp = *(const float4*)(&p_sh[hc][jj]);
            int j0 = i4.x & 0xffff, j1 = i4.x >> 16;
            int j2 = i4.y & 0xffff, j3 = i4.y >> 16;
            unsigned long long p2a = pack_f32x2(pp.x, pp.x);
            unsigned long long p2b = pack_f32x2(pp.y, pp.y);
            unsigned long long p2c = pack_f32x2(pp.z, pp.z);
            unsigned long long p2d = pack_f32x2(pp.w, pp.w);
            uint4 h0 = hb_c[(size_t)j0 * 32];
            uint4 h1 = hb_c[(size_t)j1 * 32];
            uint4 h2 = hb_c[(size_t)j2 * 32];
            uint4 h3 = hb_c[(size_t)j3 * 32];
            ffma2_h(acc01, h0.x, p2a); ffma2_h(acc23, h0.y, p2a);
            ffma2_h(acc45, h0.z, p2a); ffma2_h(acc67, h0.w, p2a);
            ffma2_h(acc01, h1.x, p2b); ffma2_h(acc23, h1.y, p2b);
            ffma2_h(acc45, h1.z, p2b); ffma2_h(acc67, h1.w, p2b);
            ffma2_h(acc01, h2.x, p2c); ffma2_h(acc23, h2.y, p2c);
            ffma2_h(acc45, h2.z, p2c); ffma2_h(acc67, h2.w, p2c);
            ffma2_h(acc01, h3.x, p2d); ffma2_h(acc23, h3.y, p2d);
            ffma2_h(acc45, h3.z, p2d); ffma2_h(acc67, h3.w, p2d);
        }
        for (; jj < hi; jj++) {
            int j = nbr[base + jj];
            float pv = p_sh[hc][jj];
            unsigned long long p2 = pack_f32x2(pv, pv);
            uint4 hv = hb_c[(size_t)j * 32];
            ffma2_h(acc01, hv.x, p2); ffma2_h(acc23, hv.y, p2);
            ffma2_h(acc45, hv.z, p2); ffma2_h(acc67, hv.w, p2);
        }
        __syncthreads();
    }

    // ---- reductions ----
#pragma unroll
    for (int h = 0; h < HEADS; h++)
#pragma unroll
        for (int d = 16; d; d >>= 1)
            sum[h] += __shfl_xor_sync(0xffffffffu, sum[h], d);
    if (lane == 0)
#pragma unroll
        for (int h = 0; h < HEADS; h++) red_sh[h][wid] = sum[h];
    {
        float a0, a1;
        unpack_f32x2(a0, a1, acc01); acc_sh[q][c][0] = a0; acc_sh[q][c][1] = a1;
        unpack_f32x2(a0, a1, acc23); acc_sh[q][c][2] = a0; acc_sh[q][c][3] = a1;
        unpack_f32x2(a0, a1, acc45); acc_sh[q][c][4] = a0; acc_sh[q][c][5] = a1;
        unpack_f32x2(a0, a1, acc67); acc_sh[q][c][6] = a0; acc_sh[q][c][7] = a1;
    }
    __syncthreads();
    if (t < HEADS) {
        float tt = 0.f;
#pragma unroll
        for (int w = 0; w < 8; w++) tt += red_sh[t][w];
        tot_sh[t] = tt;
    }
    __syncthreads();

    float s = 0.f;
#pragma unroll
    for (int qq = 0; qq < 8; qq++) s += acc_sh[qq][t >> 3][t & 7];
    s *= (1.0f / tot_sh[t >> 6]);
    out[(size_t)row * HD + t] = s;
}

// --------------------------------------------------------------------------
extern "C" void kernel_launch(void* const* d_in, const int* in_sizes, int n_in,
                              void* d_out, int out_size) {
    const float* x     = (const float*)d_in[0];
    const int*   mask  = (const int*)d_in[1];
    const float* W     = (const float*)d_in[2];
    const float* a_src = (const float*)d_in[3];
    const float* a_dst = (const float*)d_in[4];
    float*       out   = (float*)d_out;

    csr_kernel<<<NN * 4 / 8, 256>>>(mask);
    gemm_h_kernel<<<NN / 16, 256>>>(x, W, a_src, a_dst);
    max_sj_kernel<<<1, 256>>>();
    gather_kernel<<<NN, 256>>>(out);
}